// round 16
// baseline (speedup 1.0000x reference)
#include <cuda_runtime.h>
#include <cuda_bf16.h>
#include <mma.h>
#include <cstdint>

using namespace nvcuda;

#define ROWS   8192     // BATCH*SEQLEN
#define BATCH  4
#define SEQ    2048
#define DM     1024     // d_model
#define DIN    2048     // d_inner
#define NH     32       // nheads
#define HD     64       // headdim
#define DS     16       // d_state
#define CONVD  2080     // conv dim
#define DPROJ  4160     // in-proj width
#define DPAD   4224     // padded (mult of 128)
#define CL     64       // scan chunk length
#define NCH    32       // chunks per sequence

// ---------------- scratch (static device globals; no runtime alloc) -------
__device__ __nv_bfloat16  g_zx  [(size_t)ROWS * DPAD];   // in-proj out, bf16
__device__ __nv_bfloat16  g_conv[(size_t)ROWS * CONVD];  // conv+silu out, bf16
__device__ __nv_bfloat16  g_ys  [(size_t)ROWS * DIN];    // scan out (+D*xs), bf16
__device__ __nv_bfloat16  g_xb  [(size_t)ROWS * DM];
__device__ __nv_bfloat16  g_wib [(size_t)DM * DPAD];   // W_in bf16 [k][n], zero-padded
__device__ __nv_bfloat16  g_wob [(size_t)DIN * DM];    // W_out bf16 [k][n]
__device__ __nv_bfloat16  g_ynb [(size_t)ROWS * DIN];
__device__ float          g_S   [(size_t)BATCH*NH*NCH*HD*DS];
__device__ float          g_Hs  [(size_t)BATCH*NH*NCH*HD*DS];
__device__ float          g_P   [(size_t)BATCH*NH*NCH];

// ================= helpers =================================================
__device__ __forceinline__ void cp16(void* smem, const void* g) {
    unsigned s = (unsigned)__cvta_generic_to_shared(smem);
    asm volatile("cp.async.ca.shared.global [%0], [%1], 16;\n" :: "r"(s), "l"(g));
}
#define CP_COMMIT() asm volatile("cp.async.commit_group;\n" ::: "memory")
#define CP_WAIT(n)  asm volatile("cp.async.wait_group %0;\n" :: "n"(n) : "memory")

// ================= bf16 3-stage GEMM: C[M,N]=A[M,K]@B[K,N] =================
#define AROW  40
#define BROW  136
#define A_H   (128 * AROW)
#define B_H   (32 * BROW)
#define STG_H (A_H + B_H)
#define SMEM_GEMM (3 * STG_H * 2)

__global__ void __launch_bounds__(128, 2)
gemm_bf16(const __nv_bfloat16* __restrict__ A, const __nv_bfloat16* __restrict__ B,
          float* __restrict__ C, int K, int lda, int ldb, int ldc,
          const float* __restrict__ xres, const float* __restrict__ ls,
          __nv_bfloat16* __restrict__ Cb)
{
    extern __shared__ __nv_bfloat16 sm[];
    const int tid = threadIdx.x;
    const int wid = tid >> 5;
    const int lid = tid & 31;
    const int wm  = wid >> 1;
    const int wn  = wid & 1;
    const int m0  = blockIdx.y << 7;
    const int n0  = blockIdx.x << 7;

    wmma::fragment<wmma::accumulator, 16, 16, 16, float> acc[4][4];
#pragma unroll
    for (int i = 0; i < 4; i++)
#pragma unroll
        for (int j = 0; j < 4; j++) wmma::fill_fragment(acc[i][j], 0.0f);

#define LOAD_TILE(buf, k0)                                                       \
    {                                                                            \
        __nv_bfloat16* sA = sm + (buf) * STG_H;                                  \
        __nv_bfloat16* sB = sA + A_H;                                            \
        _Pragma("unroll")                                                        \
        for (int it = 0; it < 4; ++it) {                                         \
            int idx = tid + it * 128;                                            \
            int r   = idx >> 2;                                                  \
            int c   = (idx & 3) << 3;                                            \
            cp16(sA + r * AROW + c, A + (size_t)(m0 + r) * lda + (k0) + c);      \
        }                                                                        \
        _Pragma("unroll")                                                        \
        for (int it = 0; it < 4; ++it) {                                         \
            int idx = tid + it * 128;                                            \
            int r   = idx >> 4;                                                  \
            int c   = (idx & 15) << 3;                                           \
            cp16(sB + r * BROW + c, B + (size_t)((k0) + r) * ldb + n0 + c);      \
        }                                                                        \
        CP_COMMIT();                                                             \
    }

    const int KT = K >> 5;
    LOAD_TILE(0, 0);
    LOAD_TILE(1, 32);

    int buf = 0;
    for (int kt = 0; kt < KT; kt++) {
        if (kt + 2 < KT) CP_WAIT(1); else CP_WAIT(0);
        __syncthreads();
        if (kt + 2 < KT) {
            int nbuf = buf + 2; if (nbuf >= 3) nbuf -= 3;
            LOAD_TILE(nbuf, (kt + 2) << 5);
        }

        const __nv_bfloat16* sA = sm + buf * STG_H + (wm * 64) * AROW;
        const __nv_bfloat16* sB = sm + buf * STG_H + A_H + wn * 64;
#pragma unroll
        for (int kk = 0; kk < 32; kk += 16) {
            wmma::fragment<wmma::matrix_a, 16, 16, 16, __nv_bfloat16,
                           wmma::row_major> af[4];
#pragma unroll
            for (int i = 0; i < 4; i++)
                wmma::load_matrix_sync(af[i], sA + (i * 16) * AROW + kk, AROW);
#pragma unroll
            for (int j = 0; j < 4; j++) {
                wmma::fragment<wmma::matrix_b, 16, 16, 16, __nv_bfloat16,
                               wmma::row_major> bf;
                wmma::load_matrix_sync(bf, sB + kk * BROW + j * 16, BROW);
#pragma unroll
                for (int i = 0; i < 4; i++)
                    wmma::mma_sync(acc[i][j], af[i], bf, acc[i][j]);
            }
        }
        buf = (buf == 2) ? 0 : buf + 1;
    }
#undef LOAD_TILE

    if (Cb != nullptr) {
        __syncthreads();
        float* scr = reinterpret_cast<float*>(sm) + wid * 256;
        const int rr = lid >> 1;
        const int cc = (lid & 1) << 3;
#pragma unroll
        for (int i = 0; i < 4; i++)
#pragma unroll
            for (int j = 0; j < 4; j++) {
                wmma::store_matrix_sync(scr, acc[i][j], 16, wmma::mem_row_major);
                __syncwarp();
                int r = m0 + wm * 64 + i * 16 + rr;
                int c = n0 + wn * 64 + j * 16 + cc;
                const float* sv = scr + rr * 16 + cc;
                __nv_bfloat162 o[4];
#pragma unroll
                for (int q = 0; q < 4; q++)
                    o[q] = __floats2bfloat162_rn(sv[q * 2], sv[q * 2 + 1]);
                *reinterpret_cast<uint4*>(Cb + (size_t)r * ldc + c) =
                    *reinterpret_cast<uint4*>(o);
                __syncwarp();
            }
    } else if (xres == nullptr) {
#pragma unroll
        for (int i = 0; i < 4; i++)
#pragma unroll
            for (int j = 0; j < 4; j++) {
                int r = m0 + wm * 64 + i * 16;
                int c = n0 + wn * 64 + j * 16;
                wmma::store_matrix_sync(C + (size_t)r * ldc + c, acc[i][j], ldc,
                                        wmma::mem_row_major);
            }
    } else {
        __syncthreads();
        float* scr = reinterpret_cast<float*>(sm) + wid * 256;
        const int rr = lid >> 1;
        const int cc = (lid & 1) << 3;
#pragma unroll
        for (int i = 0; i < 4; i++)
#pragma unroll
            for (int j = 0; j < 4; j++) {
                wmma::store_matrix_sync(scr, acc[i][j], 16, wmma::mem_row_major);
                __syncwarp();
                int r = m0 + wm * 64 + i * 16 + rr;
                int c = n0 + wn * 64 + j * 16 + cc;
                const float* xs = xres + (size_t)r * ldc + c;
                const float* sv = scr + rr * 16 + cc;
                float4 o0, o1;
                o0.x = xs[0] + sv[0] * ls[c + 0];
                o0.y = xs[1] + sv[1] * ls[c + 1];
                o0.z = xs[2] + sv[2] * ls[c + 2];
                o0.w = xs[3] + sv[3] * ls[c + 3];
                o1.x = xs[4] + sv[4] * ls[c + 4];
                o1.y = xs[5] + sv[5] * ls[c + 5];
                o1.z = xs[6] + sv[6] * ls[c + 6];
                o1.w = xs[7] + sv[7] * ls[c + 7];
                float* dst = C + (size_t)r * ldc + c;
                *reinterpret_cast<float4*>(dst)     = o0;
                *reinterpret_cast<float4*>(dst + 4) = o1;
                __syncwarp();
            }
    }
}

// ================= converters ==============================================
__global__ void cvt_plain(const float* __restrict__ src, __nv_bfloat16* __restrict__ dst, int n)
{
    int i = blockIdx.x * blockDim.x + threadIdx.x;
    if (i < n) dst[i] = __float2bfloat16(src[i]);
}
__global__ void cvt_pad(const float* __restrict__ src, __nv_bfloat16* __restrict__ dst)
{
    int i = blockIdx.x * blockDim.x + threadIdx.x;
    if (i >= DM * DPAD) return;
    int r = i / DPAD, c = i - r * DPAD;
    dst[i] = __float2bfloat16(c < DPROJ ? src[(size_t)r * DPROJ + c] : 0.0f);
}

// ====== causal depthwise conv1d + silu (vectorized: 8 channels/thread) =====
#define CG8 (CONVD / 8)    // 260 channel-groups
__global__ void conv_kernel(const __nv_bfloat16* __restrict__ zx,
                            const float* __restrict__ cw,
                            const float* __restrict__ cb,
                            __nv_bfloat16* __restrict__ convout)
{
    int idx = blockIdx.x * blockDim.x + threadIdx.x;
    if (idx >= ROWS * CG8) return;
    int row = idx / CG8;
    int c0  = (idx - row * CG8) << 3;
    int b   = row >> 11;
    int l   = row & 2047;

    // 4 window rows of 8 bf16 each
    float v[4][8];
#pragma unroll
    for (int k = 0; k < 4; k++) {
        int lt = l + k - 3;
        if (lt >= 0) {
            uint4 raw = *reinterpret_cast<const uint4*>(
                zx + (size_t)(b * SEQ + lt) * DPAD + DIN + c0);
            const __nv_bfloat16* hp = reinterpret_cast<const __nv_bfloat16*>(&raw);
#pragma unroll
            for (int j = 0; j < 8; j++) v[k][j] = __bfloat162float(hp[j]);
        } else {
#pragma unroll
            for (int j = 0; j < 8; j++) v[k][j] = 0.0f;
        }
    }

    __nv_bfloat16 o[8];
#pragma unroll
    for (int j = 0; j < 8; j++) {
        const float4 w = *reinterpret_cast<const float4*>(cw + (c0 + j) * 4);
        float acc = cb[c0 + j] + v[0][j] * w.x + v[1][j] * w.y
                  + v[2][j] * w.z + v[3][j] * w.w;
        o[j] = __float2bfloat16(acc / (1.0f + __expf(-acc)));
    }
    *reinterpret_cast<uint4*>(convout + (size_t)row * CONVD + c0) =
        *reinterpret_cast<uint4*>(o);
}

// ================= chunked SSM scan (dt/dA computed inline) =================
__global__ void __launch_bounds__(64)
scanA(const __nv_bfloat16* __restrict__ convout, const __nv_bfloat16* __restrict__ zx,
      const float* __restrict__ dt_bias, const float* __restrict__ A_log,
      float* __restrict__ S, float* __restrict__ P)
{
    int blk = blockIdx.x;
    int bh  = blk / NCH, ch = blk & (NCH - 1);
    int b   = bh >> 5,  h  = bh & 31;
    int p   = threadIdx.x;
    const size_t rowbase = (size_t)b * SEQ + ch * CL;
    const float bias = dt_bias[h];
    const float Aneg = -__expf(A_log[h]);

    float hst[DS];
#pragma unroll
    for (int n = 0; n < DS; n++) hst[n] = 0.0f;
    float pacc = 1.0f;

    __shared__ __align__(16) float sB[32][DS];
    __shared__ float sdt[32], sdA[32];

    for (int t0 = 0; t0 < CL; t0 += 32) {
        for (int i = p; i < 32 * DS; i += 64) {
            int tt = i >> 4, n = i & 15;
            sB[tt][n] = __bfloat162float(convout[(rowbase + t0 + tt) * CONVD + DIN + n]);
        }
        for (int i = p; i < 32; i += 64) {
            float v = __bfloat162float(zx[(rowbase + t0 + i) * DPAD + DIN + CONVD + h]) + bias;
            float d = (v > 20.0f) ? v : log1pf(__expf(v));
            sdt[i] = d;
            sdA[i] = __expf(d * Aneg);
        }
        float rx[32];
#pragma unroll
        for (int tt = 0; tt < 32; tt++)
            rx[tt] = __bfloat162float(convout[(rowbase + t0 + tt) * CONVD + h * HD + p]);
        __syncthreads();
#pragma unroll
        for (int tt = 0; tt < 32; tt++) {
            float dAv = sdA[tt];
            float dtx = sdt[tt] * rx[tt];
            pacc *= dAv;
            const float4* Bp = reinterpret_cast<const float4*>(sB[tt]);
#pragma unroll
            for (int q = 0; q < 4; q++) {
                float4 Bv = Bp[q];
                hst[q*4+0] = fmaf(hst[q*4+0], dAv, dtx * Bv.x);
                hst[q*4+1] = fmaf(hst[q*4+1], dAv, dtx * Bv.y);
                hst[q*4+2] = fmaf(hst[q*4+2], dAv, dtx * Bv.z);
                hst[q*4+3] = fmaf(hst[q*4+3], dAv, dtx * Bv.w);
            }
        }
        __syncthreads();
    }
    float4* Sp = reinterpret_cast<float4*>(S + (size_t)blk * (HD * DS) + p * DS);
#pragma unroll
    for (int q = 0; q < 4; q++)
        Sp[q] = make_float4(hst[q*4+0], hst[q*4+1], hst[q*4+2], hst[q*4+3]);
    if (p == 0) P[blk] = pacc;
}

__global__ void __launch_bounds__(256)
scanB(const float* __restrict__ S, const float* __restrict__ P,
      float* __restrict__ Hs)
{
    int bh  = blockIdx.x;
    int tid = threadIdx.x;
    float4 H = make_float4(0.f, 0.f, 0.f, 0.f);
    for (int c = 0; c < NCH; c++) {
        size_t off = ((size_t)bh * NCH + c) * (HD * DS) + tid * 4;
        *reinterpret_cast<float4*>(Hs + off) = H;
        float4 sv = *reinterpret_cast<const float4*>(S + off);
        float pc = P[bh * NCH + c];
        H.x = H.x * pc + sv.x;
        H.y = H.y * pc + sv.y;
        H.z = H.z * pc + sv.z;
        H.w = H.w * pc + sv.w;
    }
}

__global__ void __launch_bounds__(64)
scanC(const __nv_bfloat16* __restrict__ convout, const __nv_bfloat16* __restrict__ zx,
      const float* __restrict__ dt_bias, const float* __restrict__ A_log,
      const float* __restrict__ Hs, const float* __restrict__ Dp,
      __nv_bfloat16* __restrict__ ys)
{
    int blk = blockIdx.x;
    int bh  = blk / NCH, ch = blk & (NCH - 1);
    int b   = bh >> 5,  h  = bh & 31;
    int p   = threadIdx.x;
    const size_t rowbase = (size_t)b * SEQ + ch * CL;
    const float Dv = Dp[h];
    const float bias = dt_bias[h];
    const float Aneg = -__expf(A_log[h]);

    float hst[DS];
    {
        const float4* Hp = reinterpret_cast<const float4*>(
            Hs + (size_t)blk * (HD * DS) + p * DS);
#pragma unroll
        for (int q = 0; q < 4; q++) {
            float4 v = Hp[q];
            hst[q*4+0] = v.x; hst[q*4+1] = v.y; hst[q*4+2] = v.z; hst[q*4+3] = v.w;
        }
    }

    __shared__ __align__(16) float sB[32][DS];
    __shared__ __align__(16) float sC[32][DS];
    __shared__ float sdt[32], sdA[32];

    for (int t0 = 0; t0 < CL; t0 += 32) {
        for (int i = p; i < 32 * DS; i += 64) {
            int tt = i >> 4, n = i & 15;
            size_t r = (rowbase + t0 + tt) * CONVD;
            sB[tt][n] = __bfloat162float(convout[r + DIN + n]);
            sC[tt][n] = __bfloat162float(convout[r + DIN + DS + n]);
        }
        for (int i = p; i < 32; i += 64) {
            float v = __bfloat162float(zx[(rowbase + t0 + i) * DPAD + DIN + CONVD + h]) + bias;
            float d = (v > 20.0f) ? v : log1pf(__expf(v));
            sdt[i] = d;
            sdA[i] = __expf(d * Aneg);
        }
        float rx[32];
#pragma unroll
        for (int tt = 0; tt < 32; tt++)
            rx[tt] = __bfloat162float(convout[(rowbase + t0 + tt) * CONVD + h * HD + p]);
        __syncthreads();
#pragma unroll
        for (int tt = 0; tt < 32; tt++) {
            float dAv = sdA[tt];
            float dtx = sdt[tt] * rx[tt];
            const float4* Bp = reinterpret_cast<const float4*>(sB[tt]);
            const float4* Cp = reinterpret_cast<const float4*>(sC[tt]);
            float yp0 = 0.f, yp1 = 0.f, yp2 = 0.f, yp3 = 0.f;
#pragma unroll
            for (int q = 0; q < 4; q++) {
                float4 Bv = Bp[q];
                float4 Cv = Cp[q];
                hst[q*4+0] = fmaf(hst[q*4+0], dAv, dtx * Bv.x); yp0 += hst[q*4+0] * Cv.x;
                hst[q*4+1] = fmaf(hst[q*4+1], dAv, dtx * Bv.y); yp1 += hst[q*4+1] * Cv.y;
                hst[q*4+2] = fmaf(hst[q*4+2], dAv, dtx * Bv.z); yp2 += hst[q*4+2] * Cv.z;
                hst[q*4+3] = fmaf(hst[q*4+3], dAv, dtx * Bv.w); yp3 += hst[q*4+3] * Cv.w;
            }
            float y = (yp0 + yp1) + (yp2 + yp3) + Dv * rx[tt];
            ys[(rowbase + t0 + tt) * DIN + h * HD + p] = __float2bfloat16(y);
        }
        __syncthreads();
    }
}

// ================= gate + RMSNorm -> bf16 ==================================
__global__ void __launch_bounds__(256)
post_kernel(const __nv_bfloat16* __restrict__ ys,
            const __nv_bfloat16* __restrict__ zx, const float* __restrict__ nw,
            __nv_bfloat16* __restrict__ yn)
{
    int row = blockIdx.x;
    int tid = threadIdx.x;
    __shared__ float wsum[8];

    float vals[8];
    float ss = 0.0f;
#pragma unroll
    for (int i = 0; i < 8; i++) {
        int c = tid + i * 256;
        float yv = __bfloat162float(ys[(size_t)row * DIN + c]);
        float z  = __bfloat162float(zx[(size_t)row * DPAD + c]);
        float g  = z / (1.0f + __expf(-z));
        float v  = yv * g;
        vals[i] = v;
        ss += v * v;
    }
#pragma unroll
    for (int o = 16; o > 0; o >>= 1) ss += __shfl_xor_sync(0xffffffffu, ss, o);
    if ((tid & 31) == 0) wsum[tid >> 5] = ss;
    __syncthreads();
    float tot = 0.0f;
#pragma unroll
    for (int w = 0; w < 8; w++) tot += wsum[w];
    float scale = rsqrtf(tot * (1.0f / DIN) + 1e-5f);
#pragma unroll
    for (int i = 0; i < 8; i++) {
        int c = tid + i * 256;
        yn[(size_t)row * DIN + c] = __float2bfloat16(vals[i] * scale * nw[c]);
    }
}

// ===========================================================================
extern "C" void kernel_launch(void* const* d_in, const int* in_sizes, int n_in,
                              void* d_out, int out_size)
{
    const float* x       = (const float*)d_in[0];
    const float* W_in    = (const float*)d_in[1];
    const float* conv_w  = (const float*)d_in[2];
    const float* conv_b  = (const float*)d_in[3];
    const float* dt_bias = (const float*)d_in[4];
    const float* A_log   = (const float*)d_in[5];
    const float* D_param = (const float*)d_in[6];
    const float* norm_w  = (const float*)d_in[7];
    const float* W_out   = (const float*)d_in[8];
    const float* lscale  = (const float*)d_in[9];
    float* out = (float*)d_out;

    float *S, *Hs, *P;
    __nv_bfloat16 *zx, *conv, *ys, *xb, *wib, *wob, *ynb;
    cudaGetSymbolAddress((void**)&zx,   g_zx);
    cudaGetSymbolAddress((void**)&conv, g_conv);
    cudaGetSymbolAddress((void**)&ys,   g_ys);
    cudaGetSymbolAddress((void**)&S,    g_S);
    cudaGetSymbolAddress((void**)&Hs,   g_Hs);
    cudaGetSymbolAddress((void**)&P,    g_P);
    cudaGetSymbolAddress((void**)&xb,   g_xb);
    cudaGetSymbolAddress((void**)&wib,  g_wib);
    cudaGetSymbolAddress((void**)&wob,  g_wob);
    cudaGetSymbolAddress((void**)&ynb,  g_ynb);

    cudaFuncSetAttribute(gemm_bf16, cudaFuncAttributeMaxDynamicSharedMemorySize,
                         SMEM_GEMM);

    // 0) converters
    cvt_plain<<<(ROWS * DM + 255) / 256, 256>>>(x, xb, ROWS * DM);
    cvt_pad  <<<(DM * DPAD + 255) / 256, 256>>>(W_in, wib);
    cvt_plain<<<(DIN * DM + 255) / 256, 256>>>(W_out, wob, DIN * DM);

    // 1) in-proj GEMM -> zx bf16 [8192,4224]
    gemm_bf16<<<dim3(DPAD / 128, ROWS / 128), 128, SMEM_GEMM>>>(
        xb, wib, nullptr, DM, DM, DPAD, DPAD, nullptr, nullptr, zx);
    // 2) conv1d + silu -> bf16 (8 channels/thread)
    conv_kernel<<<(ROWS * CG8 + 255) / 256, 256>>>(zx, conv_w, conv_b, conv);
    // 3) chunked SSM scan (NCH=32, CL=64); dt/dA inline; scanC folds D*xs
    scanA<<<BATCH * NH * NCH, 64>>>(conv, zx, dt_bias, A_log, S, P);
    scanB<<<BATCH * NH, 256>>>(S, P, Hs);
    scanC<<<BATCH * NH * NCH, 64>>>(conv, zx, dt_bias, A_log, Hs, D_param, ys);
    // 4) gate + RMSNorm -> bf16
    post_kernel<<<ROWS, 256>>>(ys, zx, norm_w, ynb);
    // 5) out-proj GEMM fused with residual+layer_scale -> out
    gemm_bf16<<<dim3(DM / 128, ROWS / 128), 128, SMEM_GEMM>>>(
        ynb, wob, out, DIN, DIN, DM, DM, x, lscale, nullptr);
}

// round 17
// speedup vs baseline: 1.1158x; 1.1158x over previous
#include <cuda_runtime.h>
#include <cuda_bf16.h>
#include <mma.h>
#include <cstdint>

using namespace nvcuda;

#define ROWS   8192     // BATCH*SEQLEN
#define BATCH  4
#define SEQ    2048
#define DM     1024     // d_model
#define DIN    2048     // d_inner
#define NH     32       // nheads
#define HD     64       // headdim
#define DS     16       // d_state
#define CONVD  2080     // conv dim
#define DPROJ  4160     // in-proj width
#define DPAD   4224     // padded (mult of 128)
#define CL     64       // scan chunk length
#define NCH    32       // chunks per sequence

// ---------------- scratch (static device globals; no runtime alloc) -------
__device__ __nv_bfloat16  g_zx  [(size_t)ROWS * DPAD];   // in-proj out, bf16
__device__ __nv_bfloat16  g_conv[(size_t)ROWS * CONVD];  // conv+silu out, bf16
__device__ float          g_dt  [(size_t)ROWS * NH];
__device__ float          g_dA  [(size_t)ROWS * NH];
__device__ __nv_bfloat16  g_ys  [(size_t)ROWS * DIN];    // scan out (+D*xs), bf16
__device__ __nv_bfloat16  g_xb  [(size_t)ROWS * DM];
__device__ __nv_bfloat16  g_wib [(size_t)DM * DPAD];   // W_in bf16 [k][n], zero-padded
__device__ __nv_bfloat16  g_wob [(size_t)DIN * DM];    // W_out bf16 [k][n]
__device__ __nv_bfloat16  g_ynb [(size_t)ROWS * DIN];
__device__ float          g_S   [(size_t)BATCH*NH*NCH*HD*DS];
__device__ float          g_Hs  [(size_t)BATCH*NH*NCH*HD*DS];
__device__ float          g_P   [(size_t)BATCH*NH*NCH];

// ================= helpers =================================================
__device__ __forceinline__ void cp16(void* smem, const void* g) {
    unsigned s = (unsigned)__cvta_generic_to_shared(smem);
    asm volatile("cp.async.ca.shared.global [%0], [%1], 16;\n" :: "r"(s), "l"(g));
}
#define CP_COMMIT() asm volatile("cp.async.commit_group;\n" ::: "memory")
#define CP_WAIT(n)  asm volatile("cp.async.wait_group %0;\n" :: "n"(n) : "memory")

// ================= bf16 3-stage GEMM: C[M,N]=A[M,K]@B[K,N] =================
#define AROW  40
#define BROW  136
#define A_H   (128 * AROW)
#define B_H   (32 * BROW)
#define STG_H (A_H + B_H)
#define SMEM_GEMM (3 * STG_H * 2)

__global__ void __launch_bounds__(128, 2)
gemm_bf16(const __nv_bfloat16* __restrict__ A, const __nv_bfloat16* __restrict__ B,
          float* __restrict__ C, int K, int lda, int ldb, int ldc,
          const float* __restrict__ xres, const float* __restrict__ ls,
          __nv_bfloat16* __restrict__ Cb)
{
    extern __shared__ __nv_bfloat16 sm[];
    const int tid = threadIdx.x;
    const int wid = tid >> 5;
    const int lid = tid & 31;
    const int wm  = wid >> 1;
    const int wn  = wid & 1;
    const int m0  = blockIdx.y << 7;
    const int n0  = blockIdx.x << 7;

    wmma::fragment<wmma::accumulator, 16, 16, 16, float> acc[4][4];
#pragma unroll
    for (int i = 0; i < 4; i++)
#pragma unroll
        for (int j = 0; j < 4; j++) wmma::fill_fragment(acc[i][j], 0.0f);

#define LOAD_TILE(buf, k0)                                                       \
    {                                                                            \
        __nv_bfloat16* sA = sm + (buf) * STG_H;                                  \
        __nv_bfloat16* sB = sA + A_H;                                            \
        _Pragma("unroll")                                                        \
        for (int it = 0; it < 4; ++it) {                                         \
            int idx = tid + it * 128;                                            \
            int r   = idx >> 2;                                                  \
            int c   = (idx & 3) << 3;                                            \
            cp16(sA + r * AROW + c, A + (size_t)(m0 + r) * lda + (k0) + c);      \
        }                                                                        \
        _Pragma("unroll")                                                        \
        for (int it = 0; it < 4; ++it) {                                         \
            int idx = tid + it * 128;                                            \
            int r   = idx >> 4;                                                  \
            int c   = (idx & 15) << 3;                                           \
            cp16(sB + r * BROW + c, B + (size_t)((k0) + r) * ldb + n0 + c);      \
        }                                                                        \
        CP_COMMIT();                                                             \
    }

    const int KT = K >> 5;
    LOAD_TILE(0, 0);
    LOAD_TILE(1, 32);

    int buf = 0;
    for (int kt = 0; kt < KT; kt++) {
        if (kt + 2 < KT) CP_WAIT(1); else CP_WAIT(0);
        __syncthreads();
        if (kt + 2 < KT) {
            int nbuf = buf + 2; if (nbuf >= 3) nbuf -= 3;
            LOAD_TILE(nbuf, (kt + 2) << 5);
        }

        const __nv_bfloat16* sA = sm + buf * STG_H + (wm * 64) * AROW;
        const __nv_bfloat16* sB = sm + buf * STG_H + A_H + wn * 64;
#pragma unroll
        for (int kk = 0; kk < 32; kk += 16) {
            wmma::fragment<wmma::matrix_a, 16, 16, 16, __nv_bfloat16,
                           wmma::row_major> af[4];
#pragma unroll
            for (int i = 0; i < 4; i++)
                wmma::load_matrix_sync(af[i], sA + (i * 16) * AROW + kk, AROW);
#pragma unroll
            for (int j = 0; j < 4; j++) {
                wmma::fragment<wmma::matrix_b, 16, 16, 16, __nv_bfloat16,
                               wmma::row_major> bf;
                wmma::load_matrix_sync(bf, sB + kk * BROW + j * 16, BROW);
#pragma unroll
                for (int i = 0; i < 4; i++)
                    wmma::mma_sync(acc[i][j], af[i], bf, acc[i][j]);
            }
        }
        buf = (buf == 2) ? 0 : buf + 1;
    }
#undef LOAD_TILE

    if (Cb != nullptr) {
        __syncthreads();
        float* scr = reinterpret_cast<float*>(sm) + wid * 256;
        const int rr = lid >> 1;
        const int cc = (lid & 1) << 3;
#pragma unroll
        for (int i = 0; i < 4; i++)
#pragma unroll
            for (int j = 0; j < 4; j++) {
                wmma::store_matrix_sync(scr, acc[i][j], 16, wmma::mem_row_major);
                __syncwarp();
                int r = m0 + wm * 64 + i * 16 + rr;
                int c = n0 + wn * 64 + j * 16 + cc;
                const float* sv = scr + rr * 16 + cc;
                __nv_bfloat162 o[4];
#pragma unroll
                for (int q = 0; q < 4; q++)
                    o[q] = __floats2bfloat162_rn(sv[q * 2], sv[q * 2 + 1]);
                *reinterpret_cast<uint4*>(Cb + (size_t)r * ldc + c) =
                    *reinterpret_cast<uint4*>(o);
                __syncwarp();
            }
    } else if (xres == nullptr) {
#pragma unroll
        for (int i = 0; i < 4; i++)
#pragma unroll
            for (int j = 0; j < 4; j++) {
                int r = m0 + wm * 64 + i * 16;
                int c = n0 + wn * 64 + j * 16;
                wmma::store_matrix_sync(C + (size_t)r * ldc + c, acc[i][j], ldc,
                                        wmma::mem_row_major);
            }
    } else {
        __syncthreads();
        float* scr = reinterpret_cast<float*>(sm) + wid * 256;
        const int rr = lid >> 1;
        const int cc = (lid & 1) << 3;
#pragma unroll
        for (int i = 0; i < 4; i++)
#pragma unroll
            for (int j = 0; j < 4; j++) {
                wmma::store_matrix_sync(scr, acc[i][j], 16, wmma::mem_row_major);
                __syncwarp();
                int r = m0 + wm * 64 + i * 16 + rr;
                int c = n0 + wn * 64 + j * 16 + cc;
                const float* xs = xres + (size_t)r * ldc + c;
                const float* sv = scr + rr * 16 + cc;
                float4 o0, o1;
                o0.x = xs[0] + sv[0] * ls[c + 0];
                o0.y = xs[1] + sv[1] * ls[c + 1];
                o0.z = xs[2] + sv[2] * ls[c + 2];
                o0.w = xs[3] + sv[3] * ls[c + 3];
                o1.x = xs[4] + sv[4] * ls[c + 4];
                o1.y = xs[5] + sv[5] * ls[c + 5];
                o1.z = xs[6] + sv[6] * ls[c + 6];
                o1.w = xs[7] + sv[7] * ls[c + 7];
                float* dst = C + (size_t)r * ldc + c;
                *reinterpret_cast<float4*>(dst)     = o0;
                *reinterpret_cast<float4*>(dst + 4) = o1;
                __syncwarp();
            }
    }
}

// ================= converters ==============================================
__global__ void cvt_plain(const float* __restrict__ src, __nv_bfloat16* __restrict__ dst, int n)
{
    int i = blockIdx.x * blockDim.x + threadIdx.x;
    if (i < n) dst[i] = __float2bfloat16(src[i]);
}
__global__ void cvt_pad(const float* __restrict__ src, __nv_bfloat16* __restrict__ dst)
{
    int i = blockIdx.x * blockDim.x + threadIdx.x;
    if (i >= DM * DPAD) return;
    int r = i / DPAD, c = i - r * DPAD;
    dst[i] = __float2bfloat16(c < DPROJ ? src[(size_t)r * DPROJ + c] : 0.0f);
}

// ================= dt / dA ==================================================
__global__ void dt_kernel(const __nv_bfloat16* __restrict__ zx,
                          const float* __restrict__ dt_bias,
                          const float* __restrict__ A_log,
                          float* __restrict__ dt, float* __restrict__ dA)
{
    int idx = blockIdx.x * blockDim.x + threadIdx.x;
    if (idx >= ROWS * NH) return;
    int row = idx >> 5, h = idx & 31;
    float v = __bfloat162float(zx[(size_t)row * DPAD + DIN + CONVD + h]) + dt_bias[h];
    float d = (v > 20.0f) ? v : log1pf(__expf(v));
    dt[idx] = d;
    dA[idx] = __expf(d * (-__expf(A_log[h])));
}

// ================= causal depthwise conv1d + silu (sliding window) =========
__global__ void conv_kernel(const __nv_bfloat16* __restrict__ zx,
                            const float* __restrict__ cw,
                            const float* __restrict__ cb,
                            __nv_bfloat16* __restrict__ convout)
{
    int idx = blockIdx.x * blockDim.x + threadIdx.x;
    if (idx >= (ROWS / 4) * CONVD) return;
    int rowq = idx / CONVD;
    int c    = idx - rowq * CONVD;
    int b    = rowq >> 9;
    int lq   = (rowq & 511) << 2;

    float w0 = cw[c * 4 + 0], w1 = cw[c * 4 + 1];
    float w2 = cw[c * 4 + 2], w3 = cw[c * 4 + 3];
    float bias = cb[c];

    float v[7];
#pragma unroll
    for (int j = 0; j < 7; j++) {
        int lt = lq + j - 3;
        v[j] = (lt >= 0) ? __bfloat162float(zx[(size_t)(b * SEQ + lt) * DPAD + DIN + c])
                         : 0.0f;
    }
#pragma unroll
    for (int t = 0; t < 4; t++) {
        float acc = bias + v[t] * w0 + v[t + 1] * w1 + v[t + 2] * w2 + v[t + 3] * w3;
        convout[(size_t)(b * SEQ + lq + t) * CONVD + c] =
            __float2bfloat16(acc / (1.0f + __expf(-acc)));
    }
}

// ================= chunked SSM scan ========================================
__global__ void __launch_bounds__(64)
scanA(const __nv_bfloat16* __restrict__ convout, const float* __restrict__ dt,
      const float* __restrict__ dA, float* __restrict__ S, float* __restrict__ P)
{
    int blk = blockIdx.x;
    int bh  = blk / NCH, ch = blk & (NCH - 1);
    int b   = bh >> 5,  h  = bh & 31;
    int p   = threadIdx.x;
    const size_t rowbase = (size_t)b * SEQ + ch * CL;

    float hst[DS];
#pragma unroll
    for (int n = 0; n < DS; n++) hst[n] = 0.0f;
    float pacc = 1.0f;

    __shared__ __align__(16) float sB[32][DS];
    __shared__ float sdt[32], sdA[32];

    for (int t0 = 0; t0 < CL; t0 += 32) {
        for (int i = p; i < 32 * DS; i += 64) {
            int tt = i >> 4, n = i & 15;
            sB[tt][n] = __bfloat162float(convout[(rowbase + t0 + tt) * CONVD + DIN + n]);
        }
        for (int i = p; i < 32; i += 64) {
            sdt[i] = dt[(rowbase + t0 + i) * NH + h];
            sdA[i] = dA[(rowbase + t0 + i) * NH + h];
        }
        float rx[32];
#pragma unroll
        for (int tt = 0; tt < 32; tt++)
            rx[tt] = __bfloat162float(convout[(rowbase + t0 + tt) * CONVD + h * HD + p]);
        __syncthreads();
#pragma unroll
        for (int tt = 0; tt < 32; tt++) {
            float dAv = sdA[tt];
            float dtx = sdt[tt] * rx[tt];
            pacc *= dAv;
            const float4* Bp = reinterpret_cast<const float4*>(sB[tt]);
#pragma unroll
            for (int q = 0; q < 4; q++) {
                float4 Bv = Bp[q];
                hst[q*4+0] = fmaf(hst[q*4+0], dAv, dtx * Bv.x);
                hst[q*4+1] = fmaf(hst[q*4+1], dAv, dtx * Bv.y);
                hst[q*4+2] = fmaf(hst[q*4+2], dAv, dtx * Bv.z);
                hst[q*4+3] = fmaf(hst[q*4+3], dAv, dtx * Bv.w);
            }
        }
        __syncthreads();
    }
    float4* Sp = reinterpret_cast<float4*>(S + (size_t)blk * (HD * DS) + p * DS);
#pragma unroll
    for (int q = 0; q < 4; q++)
        Sp[q] = make_float4(hst[q*4+0], hst[q*4+1], hst[q*4+2], hst[q*4+3]);
    if (p == 0) P[blk] = pacc;
}

__global__ void __launch_bounds__(256)
scanB(const float* __restrict__ S, const float* __restrict__ P,
      float* __restrict__ Hs)
{
    int bh  = blockIdx.x;
    int tid = threadIdx.x;
    float4 H = make_float4(0.f, 0.f, 0.f, 0.f);
    for (int c = 0; c < NCH; c++) {
        size_t off = ((size_t)bh * NCH + c) * (HD * DS) + tid * 4;
        *reinterpret_cast<float4*>(Hs + off) = H;
        float4 sv = *reinterpret_cast<const float4*>(S + off);
        float pc = P[bh * NCH + c];
        H.x = H.x * pc + sv.x;
        H.y = H.y * pc + sv.y;
        H.z = H.z * pc + sv.z;
        H.w = H.w * pc + sv.w;
    }
}

// scanC: replay chunk from start state, emit (y + D*xs) as bf16
__global__ void __launch_bounds__(64)
scanC(const __nv_bfloat16* __restrict__ convout, const float* __restrict__ dt,
      const float* __restrict__ dA, const float* __restrict__ Hs,
      const float* __restrict__ Dp, __nv_bfloat16* __restrict__ ys)
{
    int blk = blockIdx.x;
    int bh  = blk / NCH, ch = blk & (NCH - 1);
    int b   = bh >> 5,  h  = bh & 31;
    int p   = threadIdx.x;
    const size_t rowbase = (size_t)b * SEQ + ch * CL;
    const float Dv = Dp[h];

    float hst[DS];
    {
        const float4* Hp = reinterpret_cast<const float4*>(
            Hs + (size_t)blk * (HD * DS) + p * DS);
#pragma unroll
        for (int q = 0; q < 4; q++) {
            float4 v = Hp[q];
            hst[q*4+0] = v.x; hst[q*4+1] = v.y; hst[q*4+2] = v.z; hst[q*4+3] = v.w;
        }
    }

    __shared__ __align__(16) float sB[32][DS];
    __shared__ __align__(16) float sC[32][DS];
    __shared__ float sdt[32], sdA[32];

    for (int t0 = 0; t0 < CL; t0 += 32) {
        for (int i = p; i < 32 * DS; i += 64) {
            int tt = i >> 4, n = i & 15;
            size_t r = (rowbase + t0 + tt) * CONVD;
            sB[tt][n] = __bfloat162float(convout[r + DIN + n]);
            sC[tt][n] = __bfloat162float(convout[r + DIN + DS + n]);
        }
        for (int i = p; i < 32; i += 64) {
            sdt[i] = dt[(rowbase + t0 + i) * NH + h];
            sdA[i] = dA[(rowbase + t0 + i) * NH + h];
        }
        float rx[32];
#pragma unroll
        for (int tt = 0; tt < 32; tt++)
            rx[tt] = __bfloat162float(convout[(rowbase + t0 + tt) * CONVD + h * HD + p]);
        __syncthreads();
#pragma unroll
        for (int tt = 0; tt < 32; tt++) {
            float dAv = sdA[tt];
            float dtx = sdt[tt] * rx[tt];
            const float4* Bp = reinterpret_cast<const float4*>(sB[tt]);
            const float4* Cp = reinterpret_cast<const float4*>(sC[tt]);
            float yp0 = 0.f, yp1 = 0.f, yp2 = 0.f, yp3 = 0.f;
#pragma unroll
            for (int q = 0; q < 4; q++) {
                float4 Bv = Bp[q];
                float4 Cv = Cp[q];
                hst[q*4+0] = fmaf(hst[q*4+0], dAv, dtx * Bv.x); yp0 += hst[q*4+0] * Cv.x;
                hst[q*4+1] = fmaf(hst[q*4+1], dAv, dtx * Bv.y); yp1 += hst[q*4+1] * Cv.y;
                hst[q*4+2] = fmaf(hst[q*4+2], dAv, dtx * Bv.z); yp2 += hst[q*4+2] * Cv.z;
                hst[q*4+3] = fmaf(hst[q*4+3], dAv, dtx * Bv.w); yp3 += hst[q*4+3] * Cv.w;
            }
            float y = (yp0 + yp1) + (yp2 + yp3) + Dv * rx[tt];
            ys[(rowbase + t0 + tt) * DIN + h * HD + p] = __float2bfloat16(y);
        }
        __syncthreads();
    }
}

// ================= gate + RMSNorm -> bf16 (vectorized) ======================
__global__ void __launch_bounds__(256)
post_kernel(const __nv_bfloat16* __restrict__ ys,
            const __nv_bfloat16* __restrict__ zx, const float* __restrict__ nw,
            __nv_bfloat16* __restrict__ yn)
{
    int row = blockIdx.x;
    int tid = threadIdx.x;
    int c0  = tid << 3;                    // 8 contiguous halves per thread
    __shared__ float wsum[8];

    uint4 yraw = *reinterpret_cast<const uint4*>(ys + (size_t)row * DIN + c0);
    uint4 zraw = *reinterpret_cast<const uint4*>(zx + (size_t)row * DPAD + c0);
    const __nv_bfloat16* yh = reinterpret_cast<const __nv_bfloat16*>(&yraw);
    const __nv_bfloat16* zh = reinterpret_cast<const __nv_bfloat16*>(&zraw);

    float vals[8];
    float ss = 0.0f;
#pragma unroll
    for (int i = 0; i < 8; i++) {
        float yv = __bfloat162float(yh[i]);
        float z  = __bfloat162float(zh[i]);
        float g  = z / (1.0f + __expf(-z));
        float v  = yv * g;
        vals[i] = v;
        ss += v * v;
    }
#pragma unroll
    for (int o = 16; o > 0; o >>= 1) ss += __shfl_xor_sync(0xffffffffu, ss, o);
    if ((tid & 31) == 0) wsum[tid >> 5] = ss;
    __syncthreads();
    float tot = 0.0f;
#pragma unroll
    for (int w = 0; w < 8; w++) tot += wsum[w];
    float scale = rsqrtf(tot * (1.0f / DIN) + 1e-5f);

    float4 nw0 = *reinterpret_cast<const float4*>(nw + c0);
    float4 nw1 = *reinterpret_cast<const float4*>(nw + c0 + 4);
    const float* nwp = &nw0.x;   // contiguous on stack? avoid; use explicit
    __nv_bfloat16 o[8];
    o[0] = __float2bfloat16(vals[0] * scale * nw0.x);
    o[1] = __float2bfloat16(vals[1] * scale * nw0.y);
    o[2] = __float2bfloat16(vals[2] * scale * nw0.z);
    o[3] = __float2bfloat16(vals[3] * scale * nw0.w);
    o[4] = __float2bfloat16(vals[4] * scale * nw1.x);
    o[5] = __float2bfloat16(vals[5] * scale * nw1.y);
    o[6] = __float2bfloat16(vals[6] * scale * nw1.z);
    o[7] = __float2bfloat16(vals[7] * scale * nw1.w);
    (void)nwp;
    *reinterpret_cast<uint4*>(yn + (size_t)row * DIN + c0) =
        *reinterpret_cast<uint4*>(o);
}

// ===========================================================================
extern "C" void kernel_launch(void* const* d_in, const int* in_sizes, int n_in,
                              void* d_out, int out_size)
{
    const float* x       = (const float*)d_in[0];
    const float* W_in    = (const float*)d_in[1];
    const float* conv_w  = (const float*)d_in[2];
    const float* conv_b  = (const float*)d_in[3];
    const float* dt_bias = (const float*)d_in[4];
    const float* A_log   = (const float*)d_in[5];
    const float* D_param = (const float*)d_in[6];
    const float* norm_w  = (const float*)d_in[7];
    const float* W_out   = (const float*)d_in[8];
    const float* lscale  = (const float*)d_in[9];
    float* out = (float*)d_out;

    float *dt, *dA, *S, *Hs, *P;
    __nv_bfloat16 *zx, *conv, *ys, *xb, *wib, *wob, *ynb;
    cudaGetSymbolAddress((void**)&zx,   g_zx);
    cudaGetSymbolAddress((void**)&conv, g_conv);
    cudaGetSymbolAddress((void**)&dt,   g_dt);
    cudaGetSymbolAddress((void**)&dA,   g_dA);
    cudaGetSymbolAddress((void**)&ys,   g_ys);
    cudaGetSymbolAddress((void**)&S,    g_S);
    cudaGetSymbolAddress((void**)&Hs,   g_Hs);
    cudaGetSymbolAddress((void**)&P,    g_P);
    cudaGetSymbolAddress((void**)&xb,   g_xb);
    cudaGetSymbolAddress((void**)&wib,  g_wib);
    cudaGetSymbolAddress((void**)&wob,  g_wob);
    cudaGetSymbolAddress((void**)&ynb,  g_ynb);

    cudaFuncSetAttribute(gemm_bf16, cudaFuncAttributeMaxDynamicSharedMemorySize,
                         SMEM_GEMM);

    // 0) converters
    cvt_plain<<<(ROWS * DM + 255) / 256, 256>>>(x, xb, ROWS * DM);
    cvt_pad  <<<(DM * DPAD + 255) / 256, 256>>>(W_in, wib);
    cvt_plain<<<(DIN * DM + 255) / 256, 256>>>(W_out, wob, DIN * DM);

    // 1) in-proj GEMM -> zx bf16 [8192,4224]
    gemm_bf16<<<dim3(DPAD / 128, ROWS / 128), 128, SMEM_GEMM>>>(
        xb, wib, nullptr, DM, DM, DPAD, DPAD, nullptr, nullptr, zx);
    // 2) dt softplus + dA
    dt_kernel<<<(ROWS * NH + 255) / 256, 256>>>(zx, dt_bias, A_log, dt, dA);
    // 3) conv1d + silu -> bf16 (sliding window, 4 steps/thread)
    conv_kernel<<<((ROWS / 4) * CONVD + 255) / 256, 256>>>(zx, conv_w, conv_b, conv);
    // 4) chunked SSM scan (NCH=32, CL=64); scanC folds D*xs
    scanA<<<BATCH * NH * NCH, 64>>>(conv, dt, dA, S, P);
    scanB<<<BATCH * NH, 256>>>(S, P, Hs);
    scanC<<<BATCH * NH * NCH, 64>>>(conv, dt, dA, Hs, D_param, ys);
    // 5) gate + RMSNorm -> bf16 (vectorized)
    post_kernel<<<ROWS, 256>>>(ys, zx, norm_w, ynb);
    // 6) out-proj GEMM fused with residual+layer_scale -> out
    gemm_bf16<<<dim3(DM / 128, ROWS / 128), 128, SMEM_GEMM>>>(
        ynb, wob, out, DIN, DIN, DM, DM, x, lscale, nullptr);
}